// round 17
// baseline (speedup 1.0000x reference)
#include <cuda_runtime.h>

#define NPTS    2048
#define THREADS 256
#define NSPLIT  16                 // j-chunks per batch
#define CHUNK   (NPTS/NSPLIT)      // 128 j's per CTA
#define EPS     1e-5f
#define BIAS    1e-5f              // sq bias (diagonal-safe, absorbs dot-form cancellation)

__global__ void zero_kernel(float* __restrict__ o, int n) {
    const int i = blockIdx.x * blockDim.x + threadIdx.x;
    if (i < n) o[i] = 0.f;
}

__global__ __launch_bounds__(THREADS) void spring_kernel(
    const float* __restrict__ X, const float* __restrict__ Kp,
    const float* __restrict__ Bp, float* __restrict__ out)
{
    __shared__ float4 xs[CHUNK];
    __shared__ float  sred[CHUNK / 32][3];
    const int b   = blockIdx.y;
    const int jh  = blockIdx.z;
    const int tid = threadIdx.x;
    const float* Xb = X + (size_t)b * NPTS * 3;

    // Stage this CTA's j-chunk as (x, y, z, |p|^2); warp-reduce S_chunk partials.
    if (tid < CHUNK) {
        const int p = jh * CHUNK + tid;
        float x = Xb[3*p], y = Xb[3*p+1], z = Xb[3*p+2];
        xs[tid] = make_float4(x, y, z, fmaf(x, x, fmaf(y, y, z*z)));
        #pragma unroll
        for (int m = 16; m >= 1; m >>= 1) {
            x += __shfl_xor_sync(0xffffffffu, x, m);
            y += __shfl_xor_sync(0xffffffffu, y, m);
            z += __shfl_xor_sync(0xffffffffu, z, m);
        }
        if ((tid & 31) == 0) {
            sred[tid >> 5][0] = x; sred[tid >> 5][1] = y; sred[tid >> 5][2] = z;
        }
    }
    __syncthreads();
    float Sx = 0.f, Sy = 0.f, Sz = 0.f;
    #pragma unroll
    for (int w = 0; w < CHUNK / 32; w++) {
        Sx += sred[w][0]; Sy += sred[w][1]; Sz += sred[w][2];
    }

    const float K = *Kp;
    const float c = K * (*Bp + EPS);       // f = K - c*w,  w ~= rsqrt(sq)

    // One i per thread: pi fully in registers, accumulators need no reduction.
    const int i = blockIdx.x * THREADS + tid;
    const float px = Xb[3*i], py = Xb[3*i+1], pz = Xb[3*i+2];
    const float m2x = -2.f * px, m2y = -2.f * py, m2z = -2.f * pz;
    const float base = fmaf(px, px, fmaf(py, py, pz*pz)) + BIAS;

    float sr = 0.f, hpx = 0.f, hpy = 0.f, hpz = 0.f;

    // Warp-uniform broadcast loads: 1-phase LDS.128, trivial address math.
    //   sq = (|pi|^2 + bias - 2 pi.pj) + |pj|^2
    //   h  = (sum r)*pi - sum(r*pj)
    #pragma unroll 8
    for (int jj = 0; jj < CHUNK; jj++) {
        const float4 pj = xs[jj];
        float t = fmaf(m2x, pj.x, base);
        const float u = fmaf(m2y, pj.y, pj.w);
        t = fmaf(m2z, pj.z, t);
        const float r = rsqrtf(t + u);
        sr += r;
        hpx = fmaf(r, pj.x, hpx);
        hpy = fmaf(r, pj.y, hpy);
        hpz = fmaf(r, pj.z, hpz);
    }

    // Per-chunk contribution: K*(CHUNK*pi - S_chunk) - c*(sr*pi - hp)
    // chunk 0 additionally carries the +pi identity term.
    const float idf = (jh == 0) ? 1.f : 0.f;
    const float vx = fmaf(K, fmaf((float)CHUNK, px, -Sx), fmaf(-c, fmaf(sr, px, -hpx), idf * px));
    const float vy = fmaf(K, fmaf((float)CHUNK, py, -Sy), fmaf(-c, fmaf(sr, py, -hpy), idf * py));
    const float vz = fmaf(K, fmaf((float)CHUNK, pz, -Sz), fmaf(-c, fmaf(sr, pz, -hpz), idf * pz));

    float* o = out + ((size_t)b * NPTS + i) * 3;
    atomicAdd(&o[0], vx);
    atomicAdd(&o[1], vy);
    atomicAdd(&o[2], vz);
}

extern "C" void kernel_launch(void* const* d_in, const int* in_sizes, int n_in,
                              void* d_out, int out_size) {
    const float* X = (const float*)d_in[0];
    const float* K = (const float*)d_in[1];
    const float* B = (const float*)d_in[2];
    float* out = (float*)d_out;

    const int batch = in_sizes[0] / (NPTS * 3);

    zero_kernel<<<(out_size + 255) / 256, 256>>>(out, out_size);

    dim3 grid(NPTS / THREADS, batch, NSPLIT);   // 8 x 4 x 16 = 512 CTAs
    spring_kernel<<<grid, THREADS>>>(X, K, B, out);
}